// round 13
// baseline (speedup 1.0000x reference)
#include <cuda_runtime.h>
#include <cstdint>
#include <cstddef>

// Problem dims (fixed by the dataset)
#define B_   8192
#define T_   25
#define D0_  100
#define H1_  100
#define H2_  400
#define O_   784

// Persistent state in device globals (no allocations allowed)
__device__ float g_m1[B_ * H1_];
__device__ float g_m2[B_ * H2_];
__device__ float g_m3[B_ * O_];
__device__ float g_s1[B_ * H1_];
__device__ float g_s2[B_ * H2_];
// Split-K partial buffers for layer 1
__device__ float g_p0[B_ * H1_];
__device__ float g_p1[B_ * H1_];

__global__ void zero_membranes() {
    long long i = (long long)blockIdx.x * blockDim.x + threadIdx.x;
    long long stride = (long long)gridDim.x * blockDim.x;
    const long long n1 = (long long)B_ * H1_;
    const long long n2 = (long long)B_ * H2_;
    const long long n3 = (long long)B_ * O_;
    for (long long k = i; k < n1; k += stride) g_m1[k] = 0.0f;
    for (long long k = i; k < n2; k += stride) g_m2[k] = 0.0f;
    for (long long k = i; k < n3; k += stride) g_m3[k] = 0.0f;
}

// Packed f32x2 FMA: both halves are independent rn FMAs — bitwise identical to
// two scalar __fmaf_rn. ptxas never auto-generates FFMA2; must be PTX.
#define FMA2(acc, a2, b2) \
    asm("fma.rn.f32x2 %0, %1, %2, %0;" : "+l"(acc) : "l"(a2), "l"(b2))

__device__ __forceinline__ unsigned long long pack_dup(float a) {
    unsigned long long r;
    asm("mov.b64 %0, {%1, %1};" : "=l"(r) : "f"(a));
    return r;
}
__device__ __forceinline__ void unpack2(unsigned long long v, float& lo, float& hi) {
    asm("mov.b64 {%0, %1}, %2;" : "=f"(lo), "=f"(hi) : "l"(v));
}

// ---------------------------------------------------------------------------
// Tiling: BM=BN=128, BK=16, 256 threads, 8x8 micro-tile per thread.
// Arithmetic per output element: single fp32 accumulator, fold-left FMA over
// ascending k — identical to the verified R12 kernel (FFMA2 halves are
// independent per-column chains).
// ---------------------------------------------------------------------------
#define BM 128
#define BN 128
#define BK 16
#define PAD 4   // row stride BM+PAD = 132 floats (528B: 16B-aligned rows)

struct Frag { unsigned long long a2[8]; };

// Core mainloop shared by both kernels below (macro-free duplication kept simple).

__global__ __launch_bounds__(256)
void gemm_lif(const float* __restrict__ A, int lda,
              const float* __restrict__ W,
              const float* __restrict__ bias,
              float* __restrict__ mbuf,
              float* __restrict__ spk, int spk_stride,
              int N, int K)
{
    __shared__ float As[BK][BM + PAD];
    __shared__ float Ws[BK][BN + PAD];

    const int tid  = threadIdx.x;
    const int tcol = tid & 15;           // 16 cols of threads
    const int trow = tid >> 4;           // 16 rows of threads
    const int n0 = blockIdx.x * BN;
    const int m0 = blockIdx.y * BM;
    const int lk = tid & 15;
    const int lg = tid >> 4;             // 0..15

    unsigned long long acc[8][4];
    #pragma unroll
    for (int i = 0; i < 8; i++)
        #pragma unroll
        for (int j = 0; j < 4; j++)
            acc[i][j] = 0ull;

    for (int k0 = 0; k0 < K; k0 += BK) {
        const int k = k0 + lk;
        const bool kok = (k < K);
        #pragma unroll
        for (int r = 0; r < 8; r++) {
            const int m = lg + 16 * r;
            As[lk][m] = kok ? A[(size_t)(m0 + m) * lda + k] : 0.0f;
            const int n = lg + 16 * r;
            Ws[lk][n] = (kok && (n0 + n) < N) ? W[(size_t)(n0 + n) * K + k] : 0.0f;
        }
        __syncthreads();

        #pragma unroll
        for (int kk = 0; kk < BK; kk++) {
            // A fragment: 8 rows, duplicated into both f32x2 lanes
            float4 av0 = *reinterpret_cast<const float4*>(&As[kk][trow * 8]);
            float4 av1 = *reinterpret_cast<const float4*>(&As[kk][trow * 8 + 4]);
            unsigned long long a2[8];
            a2[0] = pack_dup(av0.x); a2[1] = pack_dup(av0.y);
            a2[2] = pack_dup(av0.z); a2[3] = pack_dup(av0.w);
            a2[4] = pack_dup(av1.x); a2[5] = pack_dup(av1.y);
            a2[6] = pack_dup(av1.z); a2[7] = pack_dup(av1.w);
            // W fragment: 8 cols = 4 packed col-pairs
            ulonglong2 w01 = *reinterpret_cast<const ulonglong2*>(&Ws[kk][tcol * 8]);
            ulonglong2 w23 = *reinterpret_cast<const ulonglong2*>(&Ws[kk][tcol * 8 + 4]);
            unsigned long long w2[4] = {w01.x, w01.y, w23.x, w23.y};
            #pragma unroll
            for (int i = 0; i < 8; i++) {
                FMA2(acc[i][0], a2[i], w2[0]);
                FMA2(acc[i][1], a2[i], w2[1]);
                FMA2(acc[i][2], a2[i], w2[2]);
                FMA2(acc[i][3], a2[i], w2[3]);
            }
        }
        __syncthreads();
    }

    // Epilogue: identical arithmetic to verified kernel (contracted fma form).
    #pragma unroll
    for (int i = 0; i < 8; i++) {
        const int row = m0 + trow * 8 + i;
        #pragma unroll
        for (int j = 0; j < 4; j++) {
            float c0, c1;
            unpack2(acc[i][j], c0, c1);
            #pragma unroll
            for (int h = 0; h < 2; h++) {
                const int col = n0 + tcol * 8 + 2 * j + h;
                if (col >= N) continue;
                float a = h ? c1 : c0;
                float pre = __fadd_rn(a, bias[col]);
                float cur = fmaxf(__fmul_rn(2.0f, pre), 0.0f);
                const size_t midx = (size_t)row * N + col;
                float mp  = mbuf[midx];
                float rst = (mp > 1.0f) ? 1.0f : 0.0f;
                float mn  = __fsub_rn(__fmaf_rn(0.95f, mp, cur), rst);
                mbuf[midx] = mn;
                spk[(size_t)row * spk_stride + col] = (mn > 1.0f) ? 1.0f : 0.0f;
            }
        }
    }
}

// Layer-1 split-K partial: same mainloop over k in [kbeg, kend), raw output.
__global__ __launch_bounds__(256)
void gemm_partial(const float* __restrict__ A, int lda,
                  const float* __restrict__ W,
                  float* __restrict__ out,
                  int N, int K, int kbeg, int kend)
{
    __shared__ float As[BK][BM + PAD];
    __shared__ float Ws[BK][BN + PAD];

    const int tid  = threadIdx.x;
    const int tcol = tid & 15;
    const int trow = tid >> 4;
    const int n0 = blockIdx.x * BN;
    const int m0 = blockIdx.y * BM;
    const int lk = tid & 15;
    const int lg = tid >> 4;

    unsigned long long acc[8][4];
    #pragma unroll
    for (int i = 0; i < 8; i++)
        #pragma unroll
        for (int j = 0; j < 4; j++)
            acc[i][j] = 0ull;

    for (int k0 = kbeg; k0 < kend; k0 += BK) {
        const int k = k0 + lk;
        const bool kok = (k < kend) && (k < K);
        #pragma unroll
        for (int r = 0; r < 8; r++) {
            const int m = lg + 16 * r;
            As[lk][m] = kok ? A[(size_t)(m0 + m) * lda + k] : 0.0f;
            const int n = lg + 16 * r;
            Ws[lk][n] = (kok && (n0 + n) < N) ? W[(size_t)(n0 + n) * K + k] : 0.0f;
        }
        __syncthreads();

        #pragma unroll
        for (int kk = 0; kk < BK; kk++) {
            float4 av0 = *reinterpret_cast<const float4*>(&As[kk][trow * 8]);
            float4 av1 = *reinterpret_cast<const float4*>(&As[kk][trow * 8 + 4]);
            unsigned long long a2[8];
            a2[0] = pack_dup(av0.x); a2[1] = pack_dup(av0.y);
            a2[2] = pack_dup(av0.z); a2[3] = pack_dup(av0.w);
            a2[4] = pack_dup(av1.x); a2[5] = pack_dup(av1.y);
            a2[6] = pack_dup(av1.z); a2[7] = pack_dup(av1.w);
            ulonglong2 w01 = *reinterpret_cast<const ulonglong2*>(&Ws[kk][tcol * 8]);
            ulonglong2 w23 = *reinterpret_cast<const ulonglong2*>(&Ws[kk][tcol * 8 + 4]);
            unsigned long long w2[4] = {w01.x, w01.y, w23.x, w23.y};
            #pragma unroll
            for (int i = 0; i < 8; i++) {
                FMA2(acc[i][0], a2[i], w2[0]);
                FMA2(acc[i][1], a2[i], w2[1]);
                FMA2(acc[i][2], a2[i], w2[2]);
                FMA2(acc[i][3], a2[i], w2[3]);
            }
        }
        __syncthreads();
    }

    #pragma unroll
    for (int i = 0; i < 8; i++) {
        const int row = m0 + trow * 8 + i;
        #pragma unroll
        for (int j = 0; j < 4; j++) {
            float c0, c1;
            unpack2(acc[i][j], c0, c1);
            #pragma unroll
            for (int h = 0; h < 2; h++) {
                const int col = n0 + tcol * 8 + 2 * j + h;
                if (col >= N) continue;
                out[(size_t)row * N + col] = h ? c1 : c0;
            }
        }
    }
}

// Combine split-K partials (ascending order) + LIF epilogue (contracted form).
__global__ __launch_bounds__(256)
void combine_lif(const float* __restrict__ P0,
                 const float* __restrict__ P1,
                 const float* __restrict__ bias,
                 float* __restrict__ mbuf,
                 float* __restrict__ spk, int spk_stride,
                 int M, int N)
{
    long long idx = (long long)blockIdx.x * blockDim.x + threadIdx.x;
    long long total = (long long)M * N;
    if (idx >= total) return;
    const int row = (int)(idx / N);
    const int col = (int)(idx - (long long)row * N);

    float acc = __fadd_rn(P0[idx], P1[idx]);
    float pre = __fadd_rn(acc, bias[col]);
    float cur = fmaxf(__fmul_rn(2.0f, pre), 0.0f);
    float mp  = mbuf[idx];
    float rst = (mp > 1.0f) ? 1.0f : 0.0f;
    float mn  = __fsub_rn(__fmaf_rn(0.95f, mp, cur), rst);
    mbuf[idx] = mn;
    spk[(size_t)row * spk_stride + col] = (mn > 1.0f) ? 1.0f : 0.0f;
}

extern "C" void kernel_launch(void* const* d_in, const int* in_sizes, int n_in,
                              void* d_out, int out_size)
{
    (void)in_sizes; (void)n_in; (void)out_size;
    const float* x  = (const float*)d_in[0];
    const float* W1 = (const float*)d_in[1];
    const float* b1 = (const float*)d_in[2];
    const float* W2 = (const float*)d_in[3];
    const float* b2 = (const float*)d_in[4];
    const float* W3 = (const float*)d_in[5];
    const float* b3 = (const float*)d_in[6];
    float* out = (float*)d_out;

    void* p;
    cudaGetSymbolAddress(&p, g_m1); float* m1 = (float*)p;
    cudaGetSymbolAddress(&p, g_m2); float* m2 = (float*)p;
    cudaGetSymbolAddress(&p, g_m3); float* m3 = (float*)p;
    cudaGetSymbolAddress(&p, g_s1); float* s1 = (float*)p;
    cudaGetSymbolAddress(&p, g_s2); float* s2 = (float*)p;
    cudaGetSymbolAddress(&p, g_p0); float* p0 = (float*)p;
    cudaGetSymbolAddress(&p, g_p1); float* p1 = (float*)p;

    zero_membranes<<<1024, 256>>>();

    const dim3 thr(256);
    const dim3 grid1((H1_ + BN - 1) / BN, B_ / BM);   // (1, 64)
    const dim3 grid2((H2_ + BN - 1) / BN, B_ / BM);   // (4, 64)
    const dim3 grid3((O_  + BN - 1) / BN, B_ / BM);   // (7, 64)
    const int KSPLIT = 64;
    const int combine_blocks = (B_ * H1_ + 255) / 256;

    for (int t = 0; t < T_; t++) {
        gemm_partial<<<grid1, thr>>>(x + (size_t)t * D0_, T_ * D0_, W1, p0,
                                     H1_, D0_, 0, KSPLIT);
        gemm_partial<<<grid1, thr>>>(x + (size_t)t * D0_, T_ * D0_, W1, p1,
                                     H1_, D0_, KSPLIT, D0_);
        combine_lif<<<combine_blocks, thr>>>(p0, p1, b1, m1, s1, H1_, B_, H1_);
        gemm_lif<<<grid2, thr>>>(s1, H1_, W2, b2, m2, s2, H2_, H2_, H1_);
        gemm_lif<<<grid3, thr>>>(s2, H2_, W3, b3, m3, out + (size_t)t * O_, T_ * O_,
                                 O_, H2_);
    }
}

// round 14
// speedup vs baseline: 1.0380x; 1.0380x over previous
#include <cuda_runtime.h>
#include <cstddef>

// Problem dims (fixed by the dataset)
#define B_   8192
#define T_   25
#define D0_  100
#define H1_  100
#define H2_  400
#define O_   784

// Persistent state in device globals (no allocations allowed)
__device__ float g_m1[B_ * H1_];
__device__ float g_m2[B_ * H2_];
__device__ float g_m3[B_ * O_];
__device__ float g_s1[B_ * H1_];
__device__ float g_s2[B_ * H2_];
// Split-K partial buffers for layer 1
__device__ float g_p0[B_ * H1_];
__device__ float g_p1[B_ * H1_];

__global__ void zero_membranes() {
    long long i = (long long)blockIdx.x * blockDim.x + threadIdx.x;
    long long stride = (long long)gridDim.x * blockDim.x;
    const long long n1 = (long long)B_ * H1_;
    const long long n2 = (long long)B_ * H2_;
    const long long n3 = (long long)B_ * O_;
    for (long long k = i; k < n1; k += stride) g_m1[k] = 0.0f;
    for (long long k = i; k < n2; k += stride) g_m2[k] = 0.0f;
    for (long long k = i; k < n3; k += stride) g_m3[k] = 0.0f;
}

// ---------------------------------------------------------------------------
// Layer-1 split-K partial GEMM (both halves in one launch via blockIdx.z).
// BM=BN=64, BK=16, 4x4 micro-tile. Fold-left FMA, ascending k. Raw partials.
// ---------------------------------------------------------------------------
#define BM1 64
#define BN1 64
#define BK  16

__global__ __launch_bounds__(256)
void gemm_partial_l1(const float* __restrict__ A, int lda,
                     const float* __restrict__ W,
                     float* __restrict__ out0,
                     float* __restrict__ out1,
                     int N, int K, int ksplit)
{
    __shared__ float As[BK][BM1 + 4];
    __shared__ float Ws[BK][BN1 + 4];

    const int tid  = threadIdx.x;
    const int tcol = tid & 15;
    const int trow = tid >> 4;
    const int n0 = blockIdx.x * BN1;
    const int m0 = blockIdx.y * BM1;
    const int lk = tid & 15;
    const int lr = tid >> 4;

    const int kbeg = blockIdx.z ? ksplit : 0;
    const int kend = blockIdx.z ? K : ksplit;
    float* __restrict__ out = blockIdx.z ? out1 : out0;

    float acc[4][4];
    #pragma unroll
    for (int i = 0; i < 4; i++)
        #pragma unroll
        for (int j = 0; j < 4; j++)
            acc[i][j] = 0.0f;

    for (int k0 = kbeg; k0 < kend; k0 += BK) {
        const int k = k0 + lk;
        const bool kok = (k < kend);
        #pragma unroll
        for (int r = 0; r < 4; r++) {
            const int m = m0 + lr + 16 * r;
            As[lk][lr + 16 * r] = kok ? A[(size_t)m * lda + k] : 0.0f;
            const int n = n0 + lr + 16 * r;
            Ws[lk][lr + 16 * r] = (kok && n < N) ? W[(size_t)n * K + k] : 0.0f;
        }
        __syncthreads();
        #pragma unroll
        for (int kk = 0; kk < BK; kk++) {
            float4 av = *reinterpret_cast<const float4*>(&As[kk][trow * 4]);
            float4 wv = *reinterpret_cast<const float4*>(&Ws[kk][tcol * 4]);
            float a[4] = {av.x, av.y, av.z, av.w};
            float w[4] = {wv.x, wv.y, wv.z, wv.w};
            #pragma unroll
            for (int i = 0; i < 4; i++)
                #pragma unroll
                for (int j = 0; j < 4; j++)
                    acc[i][j] = __fmaf_rn(a[i], w[j], acc[i][j]);
        }
        __syncthreads();
    }

    #pragma unroll
    for (int i = 0; i < 4; i++) {
        const int row = m0 + trow * 4 + i;
        #pragma unroll
        for (int j = 0; j < 4; j++) {
            const int col = n0 + tcol * 4 + j;
            if (col >= N) continue;
            out[(size_t)row * N + col] = acc[i][j];
        }
    }
}

// Combine split-K partials (ascending order) + LIF epilogue (contracted form).
__global__ __launch_bounds__(256)
void combine_lif(const float* __restrict__ P0,
                 const float* __restrict__ P1,
                 const float* __restrict__ bias,
                 float* __restrict__ mbuf,
                 float* __restrict__ spk, int spk_stride,
                 int M, int N)
{
    long long idx = (long long)blockIdx.x * blockDim.x + threadIdx.x;
    long long total = (long long)M * N;
    if (idx >= total) return;
    const int row = (int)(idx / N);
    const int col = (int)(idx - (long long)row * N);

    float acc = __fadd_rn(P0[idx], P1[idx]);
    float pre = __fadd_rn(acc, bias[col]);
    float cur = fmaxf(__fmul_rn(2.0f, pre), 0.0f);
    float mp  = mbuf[idx];
    float rst = (mp > 1.0f) ? 1.0f : 0.0f;
    float mn  = __fsub_rn(__fmaf_rn(0.95f, mp, cur), rst);
    mbuf[idx] = mn;
    spk[(size_t)row * spk_stride + col] = (mn > 1.0f) ? 1.0f : 0.0f;
}

// ---------------------------------------------------------------------------
// Layers 2/3: fused GEMM + LIF, 8x8 micro-tile, BM=BN=128, BK=16, 256 thr.
// Per-element arithmetic identical to verified kernel: single fp32 accumulator,
// fold-left FMA ascending k, contracted epilogue.
// ---------------------------------------------------------------------------
#define BM 128
#define BN 128
#define PAD 4

__global__ __launch_bounds__(256)
void gemm_lif8(const float* __restrict__ A, int lda,
               const float* __restrict__ W,
               const float* __restrict__ bias,
               float* __restrict__ mbuf,
               float* __restrict__ spk, int spk_stride,
               int N, int K)
{
    __shared__ float As[BK][BM + PAD];
    __shared__ float Ws[BK][BN + PAD];

    const int tid  = threadIdx.x;
    const int tcol = tid & 15;           // 16 thread-cols * 8 cols
    const int trow = tid >> 4;           // 16 thread-rows * 8 rows
    const int n0 = blockIdx.x * BN;
    const int m0 = blockIdx.y * BM;
    const int lk = tid & 15;
    const int lg = tid >> 4;             // 0..15

    float acc[8][8];
    #pragma unroll
    for (int i = 0; i < 8; i++)
        #pragma unroll
        for (int j = 0; j < 8; j++)
            acc[i][j] = 0.0f;

    for (int k0 = 0; k0 < K; k0 += BK) {
        const int k = k0 + lk;
        const bool kok = (k < K);
        #pragma unroll
        for (int r = 0; r < 8; r++) {
            const int m = lg + 16 * r;
            As[lk][m] = kok ? A[(size_t)(m0 + m) * lda + k] : 0.0f;
            const int n = lg + 16 * r;
            Ws[lk][n] = (kok && (n0 + n) < N) ? W[(size_t)(n0 + n) * K + k] : 0.0f;
        }
        __syncthreads();

        #pragma unroll
        for (int kk = 0; kk < BK; kk++) {
            float4 av0 = *reinterpret_cast<const float4*>(&As[kk][trow * 8]);
            float4 av1 = *reinterpret_cast<const float4*>(&As[kk][trow * 8 + 4]);
            float4 wv0 = *reinterpret_cast<const float4*>(&Ws[kk][tcol * 8]);
            float4 wv1 = *reinterpret_cast<const float4*>(&Ws[kk][tcol * 8 + 4]);
            float a[8] = {av0.x, av0.y, av0.z, av0.w, av1.x, av1.y, av1.z, av1.w};
            float w[8] = {wv0.x, wv0.y, wv0.z, wv0.w, wv1.x, wv1.y, wv1.z, wv1.w};
            #pragma unroll
            for (int i = 0; i < 8; i++)
                #pragma unroll
                for (int j = 0; j < 8; j++)
                    acc[i][j] = __fmaf_rn(a[i], w[j], acc[i][j]);
        }
        __syncthreads();
    }

    // Epilogue: identical arithmetic to verified kernel (contracted fma form).
    #pragma unroll
    for (int i = 0; i < 8; i++) {
        const int row = m0 + trow * 8 + i;
        #pragma unroll
        for (int j = 0; j < 8; j++) {
            const int col = n0 + tcol * 8 + j;
            if (col >= N) continue;
            float pre = __fadd_rn(acc[i][j], bias[col]);
            float cur = fmaxf(__fmul_rn(2.0f, pre), 0.0f);
            const size_t midx = (size_t)row * N + col;
            float mp  = mbuf[midx];
            float rst = (mp > 1.0f) ? 1.0f : 0.0f;
            float mn  = __fsub_rn(__fmaf_rn(0.95f, mp, cur), rst);
            mbuf[midx] = mn;
            spk[(size_t)row * spk_stride + col] = (mn > 1.0f) ? 1.0f : 0.0f;
        }
    }
}

extern "C" void kernel_launch(void* const* d_in, const int* in_sizes, int n_in,
                              void* d_out, int out_size)
{
    (void)in_sizes; (void)n_in; (void)out_size;
    const float* x  = (const float*)d_in[0];
    const float* W1 = (const float*)d_in[1];
    const float* b1 = (const float*)d_in[2];
    const float* W2 = (const float*)d_in[3];
    const float* b2 = (const float*)d_in[4];
    const float* W3 = (const float*)d_in[5];
    const float* b3 = (const float*)d_in[6];
    float* out = (float*)d_out;

    void* p;
    cudaGetSymbolAddress(&p, g_m1); float* m1 = (float*)p;
    cudaGetSymbolAddress(&p, g_m2); float* m2 = (float*)p;
    cudaGetSymbolAddress(&p, g_m3); float* m3 = (float*)p;
    cudaGetSymbolAddress(&p, g_s1); float* s1 = (float*)p;
    cudaGetSymbolAddress(&p, g_s2); float* s2 = (float*)p;
    cudaGetSymbolAddress(&p, g_p0); float* p0 = (float*)p;
    cudaGetSymbolAddress(&p, g_p1); float* p1 = (float*)p;

    zero_membranes<<<1024, 256>>>();

    const dim3 thr(256);
    const dim3 grid1((H1_ + BN1 - 1) / BN1, B_ / BM1, 2);  // (2, 128, 2) both splits
    const dim3 grid2((H2_ + BN - 1) / BN, B_ / BM);        // (4, 64)
    const dim3 grid3((O_  + BN - 1) / BN, B_ / BM);        // (7, 64)
    const int KSPLIT = 64;
    const int combine_blocks = (B_ * H1_ + 255) / 256;

    for (int t = 0; t < T_; t++) {
        gemm_partial_l1<<<grid1, thr>>>(x + (size_t)t * D0_, T_ * D0_, W1,
                                        p0, p1, H1_, D0_, KSPLIT);
        combine_lif<<<combine_blocks, thr>>>(p0, p1, b1, m1, s1, H1_, B_, H1_);
        gemm_lif8<<<grid2, thr>>>(s1, H1_, W2, b2, m2, s2, H2_, H2_, H1_);
        gemm_lif8<<<grid3, thr>>>(s2, H2_, W3, b3, m3, out + (size_t)t * O_, T_ * O_,
                                  O_, H2_);
    }
}